// round 1
// baseline (speedup 1.0000x reference)
#include <cuda_runtime.h>
#include <cstddef>

#define NW    100000
#define VD    128
#define BATCH 16384
#define KNUM  26

// 51.2 MB transposed copy of O: OT[word][v]. Static device scratch (no alloc).
__device__ float g_OT[(size_t)NW * VD];

// ---------------------------------------------------------------------------
// Kernel 1: transpose O [VD, NW] -> OT [NW, VD], tiled 32x32 via smem.
// Grid: (NW/32, VD/32) = (3125, 4). Block: (32, 8).
// ---------------------------------------------------------------------------
__global__ void transpose_kernel(const float* __restrict__ O) {
    __shared__ float tile[32][33];  // +1 pad: conflict-free transpose read
    const int w0 = blockIdx.x * 32;
    const int v0 = blockIdx.y * 32;
    const int tx = threadIdx.x;
    const int ty = threadIdx.y;

#pragma unroll
    for (int j = 0; j < 32; j += 8) {
        // coalesced along w (contiguous in O rows)
        tile[ty + j][tx] = O[(size_t)(v0 + ty + j) * NW + (w0 + tx)];
    }
    __syncthreads();
#pragma unroll
    for (int j = 0; j < 32; j += 8) {
        // coalesced along v (contiguous in OT rows)
        g_OT[(size_t)(w0 + ty + j) * VD + (v0 + tx)] = tile[tx][ty + j];
    }
}

// ---------------------------------------------------------------------------
// Kernel 2: one block (128 threads = 4 warps) per batch element b.
//   - stage d = D[doc_ids[b]] (512B, coalesced) into smem
//   - each warp takes k = wid, wid+4, ... : reads OT[word] as 32 x float4
//     (one fully coalesced 512B row), FMA + butterfly shuffle reduce.
// ---------------------------------------------------------------------------
__global__ void score_kernel(const int* __restrict__ doc_ids,
                             const int* __restrict__ tnids,
                             const float* __restrict__ D,
                             float* __restrict__ out) {
    const int b    = blockIdx.x;
    const int t    = threadIdx.x;
    const int lane = t & 31;
    const int wid  = t >> 5;

    __shared__ __align__(16) float sd[VD];
    __shared__ int swords[KNUM];

    const int doc = doc_ids[b];
    sd[t] = D[(size_t)doc * VD + t];
    if (t < KNUM) swords[t] = tnids[b * KNUM + t];
    __syncthreads();

    const float4 dv = reinterpret_cast<const float4*>(sd)[lane];

    for (int k = wid; k < KNUM; k += 4) {
        const int word = swords[k];
        const float4 w4 =
            reinterpret_cast<const float4*>(g_OT + (size_t)word * VD)[lane];
        float s = dv.x * w4.x + dv.y * w4.y + dv.z * w4.z + dv.w * w4.w;
        s += __shfl_xor_sync(0xffffffffu, s, 16);
        s += __shfl_xor_sync(0xffffffffu, s, 8);
        s += __shfl_xor_sync(0xffffffffu, s, 4);
        s += __shfl_xor_sync(0xffffffffu, s, 2);
        s += __shfl_xor_sync(0xffffffffu, s, 1);
        if (lane == 0) out[b * KNUM + k] = s;
    }
}

// ---------------------------------------------------------------------------
// Inputs (metadata order): context_ids[B] i32 (unused), doc_ids[B] i32,
// target_noise_ids[B*K] i32, D[NUM_DOCS*VD] f32, O[VD*NW] f32.
// Output: out[B*K] f32.
// ---------------------------------------------------------------------------
extern "C" void kernel_launch(void* const* d_in, const int* in_sizes, int n_in,
                              void* d_out, int out_size) {
    const int*   doc_ids = (const int*)d_in[1];
    const int*   tnids   = (const int*)d_in[2];
    const float* D       = (const float*)d_in[3];
    const float* O       = (const float*)d_in[4];
    float*       out     = (float*)d_out;

    dim3 tg(NW / 32, VD / 32);
    dim3 tb(32, 8);
    transpose_kernel<<<tg, tb>>>(O);

    score_kernel<<<BATCH, VD>>>(doc_ids, tnids, D, out);
}